// round 13
// baseline (speedup 1.0000x reference)
#include <cuda_runtime.h>
#include <math.h>

typedef unsigned long long u64;

// ---------------- device scratch (allocation-free) ----------------
__device__ float g_gi[2ull*512*768*256];     // [D][T][768][B]  (reused per layer)
__device__ float g_y0[512ull*512*256];       // [T][512][B] layer0 output (transposed)
__device__ float g_h0[2][2*256*256];         // [phase][D][J=256][B]
__device__ float g_h1[2][2*256*256];
__device__ float g_hd0[2][512*256];          // [phase][J=512][B]
__device__ float g_hd1[2][512*256];
__device__ float g_dinp[256*2];              // decoder feedback [B][2]
__device__ float g_WihT0[2*64*768];
__device__ float g_WihT1[2*512*768];
__device__ float g_WhhT0[2*256*768];
__device__ float g_WhhT1[2*256*768];
__device__ float g_dWhhT0[512*1536];
__device__ float g_dWihT1[512*1536];
__device__ float g_dWhhT1[512*1536];
__device__ u64   g_ebar[16*16];              // encoder: 16 groups, 128B apart
__device__ u64   g_dbar[8*16];               // decoder: 8 groups

// ---------------- f32x2 helpers ----------------
__device__ __forceinline__ u64 pack2(float lo, float hi) {
    u64 r; asm("mov.b64 %0, {%1,%2};" : "=l"(r) : "f"(lo), "f"(hi)); return r;
}
__device__ __forceinline__ void fma2(u64& d, u64 a, u64 b) {
    asm("fma.rn.f32x2 %0, %1, %2, %3;" : "=l"(d) : "l"(a), "l"(b), "l"(d));
}
__device__ __forceinline__ float2 unpack2(u64 v) {
    float2 f; asm("mov.b64 {%0,%1}, %2;" : "=f"(f.x), "=f"(f.y) : "l"(v)); return f;
}
__device__ __forceinline__ float sigf(float x) { return 1.f / (1.f + __expf(-x)); }

// ---------------- group barrier (monotonic ticket, per-group counter) ------
__device__ __forceinline__ void group_barrier(u64* bar, unsigned n) {
    __syncthreads();
    if (threadIdx.x == 0) {
        __threadfence();
        u64 t = atomicAdd(bar, 1ULL);
        u64 target = (t / n + 1ULL) * (u64)n;
        u64 v;
        do {
            asm volatile("ld.acquire.gpu.global.u64 %0, [%1];" : "=l"(v) : "l"(bar));
        } while (v < target);
    }
    __syncthreads();
}

// ---------------- transpose helper (32x32 tile) ----------------
__device__ __forceinline__ void tile_transpose(const float* __restrict__ in,
                                               float* __restrict__ out,
                                               int N, int K, int bx, int by) {
    __shared__ float t[32][33];
    int k0 = bx * 32, n0 = by * 32;
    int x = threadIdx.x, y = threadIdx.y;
#pragma unroll
    for (int j = 0; j < 32; j += 8) {
        int n = n0 + y + j;
        if (n < N && k0 + x < K) t[y + j][x] = in[(size_t)n * K + k0 + x];
    }
    __syncthreads();
#pragma unroll
    for (int j = 0; j < 32; j += 8) {
        int k = k0 + y + j;
        if (k < K && n0 + x < N) out[(size_t)k * N + n0 + x] = t[x][y + j];
    }
}

// ---------------- single prep kernel: all transposes + h zero --------------
// grid (16, 48, 12), block (32, 8)
__global__ void k_prep_all(const float* __restrict__ eWih0, float* __restrict__ WihT0,
                           const float* __restrict__ eWhh0, float* __restrict__ WhhT0,
                           const float* __restrict__ eWih1, float* __restrict__ WihT1,
                           const float* __restrict__ eWhh1, float* __restrict__ WhhT1,
                           const float* __restrict__ dWhh0, float* __restrict__ dWhhT0,
                           const float* __restrict__ dWih1, float* __restrict__ dWihT1,
                           const float* __restrict__ dWhh1, float* __restrict__ dWhhT1,
                           float* __restrict__ h0, float* __restrict__ h1) {
    int z = blockIdx.z, bx = blockIdx.x, by = blockIdx.y;
    if (z < 2) {
        if (bx < 2 && by < 24)
            tile_transpose(eWih0 + (size_t)z * 768 * 64, WihT0 + (size_t)z * 64 * 768,
                           768, 64, bx, by);
    } else if (z < 4) {
        if (bx < 8 && by < 24)
            tile_transpose(eWhh0 + (size_t)(z - 2) * 768 * 256, WhhT0 + (size_t)(z - 2) * 256 * 768,
                           768, 256, bx, by);
    } else if (z < 6) {
        if (by < 24)
            tile_transpose(eWih1 + (size_t)(z - 4) * 768 * 512, WihT1 + (size_t)(z - 4) * 512 * 768,
                           768, 512, bx, by);
    } else if (z < 8) {
        if (bx < 8 && by < 24)
            tile_transpose(eWhh1 + (size_t)(z - 6) * 768 * 256, WhhT1 + (size_t)(z - 6) * 256 * 768,
                           768, 256, bx, by);
    } else if (z < 11) {
        const float* in = (z == 8) ? dWhh0 : (z == 9) ? dWih1 : dWhh1;
        float* out      = (z == 8) ? dWhhT0 : (z == 9) ? dWihT1 : dWhhT1;
        tile_transpose(in, out, 1536, 512, bx, by);
    } else {
        int flat = ((bx * 48 + by) * 256) + threadIdx.y * 32 + threadIdx.x;
        for (int i = flat; i < 131072; i += 16 * 48 * 256) { h0[i] = 0.f; h1[i] = 0.f; }
    }
}

// ---------------- gi GEMM (dup-A staging + 3 CTAs/SM) ----------------
// out[d][t][col][b] = sum_k A[t,b,k] * W[d][col][k] + bih[d][col]
// MODE 0: A = x [B][T][64] (K=64); MODE 1: A = y0 [T][512][B] (K=512)
// inner k-iter: 4 LDS.64 (dup-a) + 4 LDS.64 (w pairs) + 16 FFMA2 = 24 issues.
template<int MODE>
__global__ __launch_bounds__(256, 3)
void k_gi_gemm(const float* __restrict__ A, const float* __restrict__ WT,
               const float* __restrict__ bih, float* __restrict__ out, int K) {
    __shared__ u64   As8[32 * 67];   // [kk][b] dup (a,a); stride 67 avoids conflicts
    __shared__ float Ws[32][128];
    int ct = blockIdx.x, bt = blockIdx.y;
    int d = blockIdx.z >> 9, t = blockIdx.z & 511;
    int tid = threadIdx.x;
    int bg = tid & 15, cg = tid >> 4;
    const float* Wd = WT + (size_t)d * K * 768;
    u64 acc[4][4];
#pragma unroll
    for (int i = 0; i < 4; i++)
#pragma unroll
        for (int j = 0; j < 4; j++) acc[i][j] = 0ull;

    for (int k0 = 0; k0 < K; k0 += 32) {
        if (MODE == 0) {
#pragma unroll
            for (int i = 0; i < 8; i++) {
                int e = tid + i * 256; int b = e >> 5, k = e & 31;
                float v = A[((size_t)(bt * 64 + b) * 512 + t) * 64 + k0 + k];
                As8[k * 67 + b] = pack2(v, v);
            }
        } else {
#pragma unroll
            for (int i = 0; i < 8; i++) {
                int e = tid + i * 256; int kk = e >> 6, b = e & 63;
                float v = A[((size_t)t * 512 + k0 + kk) * 256 + bt * 64 + b];
                As8[kk * 67 + b] = pack2(v, v);
            }
        }
#pragma unroll
        for (int i = 0; i < 16; i++) {
            int e = tid + i * 256; int kk = e >> 7, c = e & 127;
            Ws[kk][c] = Wd[(size_t)(k0 + kk) * 768 + ct * 128 + c];
        }
        __syncthreads();
#pragma unroll
        for (int kk = 0; kk < 32; kk++) {
            u64 w[4];
#pragma unroll
            for (int j = 0; j < 4; j++) w[j] = *(const u64*)&Ws[kk][32 * j + 2 * cg];
            u64 a[4];
#pragma unroll
            for (int i = 0; i < 4; i++) a[i] = As8[kk * 67 + bg + 16 * i];
#pragma unroll
            for (int i = 0; i < 4; i++)
#pragma unroll
                for (int j = 0; j < 4; j++) fma2(acc[i][j], a[i], w[j]);
        }
        __syncthreads();
    }
    float* outp = out + (size_t)(d * 512 + t) * 768 * 256;
#pragma unroll
    for (int j = 0; j < 4; j++) {
        int c = ct * 128 + 32 * j + 2 * cg;
        float2 bb = *(const float2*)&bih[d * 768 + c];
#pragma unroll
        for (int i = 0; i < 4; i++) {
            float2 v = unpack2(acc[i][j]);
            int b = bt * 64 + bg + 16 * i;
            outp[(size_t)c * 256 + b]       = v.x + bb.x;
            outp[(size_t)(c + 1) * 256 + b] = v.y + bb.y;
        }
    }
}

// ---------------- persistent encoder layer (R12 version, unchanged) --------
// 128 CTAs x 256 threads. CTA = (jt 0..7, group 0..15), group=(bt 0..7, d 0..1).
__global__ __launch_bounds__(256, 1)
void k_enc_layer(const float* __restrict__ WhhT, const float* __restrict__ bhh,
                 const float* __restrict__ gi, float* __restrict__ hbuf,
                 float* __restrict__ yout, u64* __restrict__ barBase) {
    extern __shared__ char sm[];
    u64*   WdA = (u64*)sm;                       // [256][32][2] g0,g1 dup
    u64*   WdB = (u64*)(sm + 131072);            // [256][32]   g2 dup
    float* Hs  = (float*)(sm + 196608);          // [256][32]
    int bx = blockIdx.x;
    int jt = bx & 7, grp = bx >> 3;
    int bt = grp & 7, d = grp >> 3;
    u64* bar = barBase + grp * 16;
    int tid = threadIdx.x;
    int pbg = tid & 7;
    int cw  = tid >> 3;
    int j = jt * 32 + cw;
    int bbase = bt * 32 + 4 * pbg;

    const float* Wp = WhhT + (size_t)d * 256 * 768;
#pragma unroll 4
    for (int i = 0; i < 96; i++) {
        int e = tid + i * 256;
        int c = e & 31, k = (e >> 5) & 255, g = e >> 13;
        float w = Wp[(size_t)k * 768 + g * 256 + jt * 32 + c];
        u64 wd = pack2(w, w);
        if (g < 2) WdA[(k * 32 + c) * 2 + g] = wd;
        else       WdB[k * 32 + c] = wd;
    }
    const float* bh = bhh + d * 768;
    float bhv[3];
#pragma unroll
    for (int g = 0; g < 3; g++) bhv[g] = bh[g * 256 + j];

    int row0 = tid >> 5, bcol = tid & 31;

    for (int s = 0; s < 512; s++) {
        const float* hsrc = hbuf + (size_t)(s & 1) * 131072 + (size_t)d * 65536;
        float*       hdst = hbuf + (size_t)((s + 1) & 1) * 131072 + (size_t)d * 65536;
        int t = d ? (511 - s) : s;
        const float* gp = gi + (size_t)(d * 512 + t) * 768 * 256;
        float4 gx[3];
#pragma unroll
        for (int g = 0; g < 3; g++)
            gx[g] = *(const float4*)&gp[((size_t)(g * 256 + j)) * 256 + bbase];
        float tmp[32];
#pragma unroll
        for (int i = 0; i < 32; i++)
            tmp[i] = hsrc[(size_t)(row0 + 8 * i) * 256 + bt * 32 + bcol];
#pragma unroll
        for (int i = 0; i < 32; i++)
            Hs[(row0 + 8 * i) * 32 + bcol] = tmp[i];
        __syncthreads();

        u64 acc[3][2];
#pragma unroll
        for (int g = 0; g < 3; g++) { acc[g][0] = 0ull; acc[g][1] = 0ull; }

#pragma unroll 16
        for (int kk = 0; kk < 256; kk++) {
            ulonglong2 av  = *(const ulonglong2*)&Hs[kk * 32 + 4 * pbg];
            ulonglong2 w01 = *(const ulonglong2*)&WdA[((size_t)kk * 32 + cw) * 2];
            u64        w2  = WdB[kk * 32 + cw];
            fma2(acc[0][0], av.x, w01.x); fma2(acc[0][1], av.y, w01.x);
            fma2(acc[1][0], av.x, w01.y); fma2(acc[1][1], av.y, w01.y);
            fma2(acc[2][0], av.x, w2);    fma2(acc[2][1], av.y, w2);
        }
        float4 hold = *(const float4*)&Hs[j * 32 + 4 * pbg];
        float hlds[4] = {hold.x, hold.y, hold.z, hold.w};
        float rh[4], zh[4], nh[4];
        { float2 a = unpack2(acc[0][0]), b2 = unpack2(acc[0][1]);
          rh[0] = a.x; rh[1] = a.y; rh[2] = b2.x; rh[3] = b2.y; }
        { float2 a = unpack2(acc[1][0]), b2 = unpack2(acc[1][1]);
          zh[0] = a.x; zh[1] = a.y; zh[2] = b2.x; zh[3] = b2.y; }
        { float2 a = unpack2(acc[2][0]), b2 = unpack2(acc[2][1]);
          nh[0] = a.x; nh[1] = a.y; nh[2] = b2.x; nh[3] = b2.y; }
        float gxr[4] = {gx[0].x, gx[0].y, gx[0].z, gx[0].w};
        float gxz[4] = {gx[1].x, gx[1].y, gx[1].z, gx[1].w};
        float gxn[4] = {gx[2].x, gx[2].y, gx[2].z, gx[2].w};
        float res[4];
#pragma unroll
        for (int q = 0; q < 4; q++) {
            float r = sigf(rh[q] + bhv[0] + gxr[q]);
            float z = sigf(zh[q] + bhv[1] + gxz[q]);
            float n = tanhf(gxn[q] + r * (nh[q] + bhv[2]));
            res[q] = (1.f - z) * n + z * hlds[q];
        }
        float4 out4 = make_float4(res[0], res[1], res[2], res[3]);
        *(float4*)&hdst[(size_t)j * 256 + bbase] = out4;
        if (yout)
            *(float4*)&yout[((size_t)t * 512 + d * 256 + j) * 256 + bbase] = out4;
        group_barrier(bar, 8);
    }
}

// ---------------- persistent decoder (20 steps, 2 layers + fc) -------------
__global__ __launch_bounds__(128, 1)
void k_decoder(const float* __restrict__ dWhhT0, const float* __restrict__ dBhh0,
               const float* __restrict__ dWih0,  const float* __restrict__ dBih0,
               const float* __restrict__ dWihT1, const float* __restrict__ dWhhT1,
               const float* __restrict__ dBih1,  const float* __restrict__ dBhh1,
               const float* __restrict__ fcW,    const float* __restrict__ fcb,
               const float* __restrict__ stok,
               float* __restrict__ hd0, float* __restrict__ hd1,
               float* __restrict__ dinp, float* __restrict__ out,
               u64* __restrict__ barBase) {
    extern __shared__ char dsm[];
    u64*   Ws8  = (u64*)dsm;                       // 24576 B
    u64*   WXs8 = (u64*)(dsm + 24576);             // 24576 B
    float* Hs   = (float*)(dsm + 49152);           // 4096 B
    float* Xs   = (float*)(dsm + 53248);           // 4096 B
    float* red  = (float*)(dsm + 57344);           // 1024 B
    int bx = blockIdx.x;
    int ct = bx & 15, bt = bx >> 4;
    u64* bar = barBase + bt * 16;
    int tid = threadIdx.x;
    int pbg = tid & 7, cg = tid >> 3;
    int row0 = tid >> 5, bcol = tid & 31;

    float w0a[3][2], w0b[3][2], bi0[3][2], bh0[3][2], bi1[3][2], bh1[3][2];
#pragma unroll
    for (int g = 0; g < 3; g++)
#pragma unroll
        for (int u = 0; u < 2; u++) {
            int c = g * 512 + ct * 32 + cg + 16 * u;
            w0a[g][u] = dWih0[c * 2];
            w0b[g][u] = dWih0[c * 2 + 1];
            bi0[g][u] = dBih0[c];
            bh0[g][u] = dBhh0[c];
            bi1[g][u] = dBih1[c];
            bh1[g][u] = dBhh1[c];
        }

    for (int s = 0; s < 20; s++) {
        const float* h0s = hd0 + (size_t)(s & 1) * 131072;
        float*       h0d = hd0 + (size_t)((s + 1) & 1) * 131072;
        const float* h1s = hd1 + (size_t)(s & 1) * 131072;
        float*       h1d = hd1 + (size_t)((s + 1) & 1) * 131072;
        const float* inp = s ? dinp : stok;
        int istr = s ? 2 : 0;

        // ================= layer 0 =================
        u64 acc[3][2][2];
#pragma unroll
        for (int g = 0; g < 3; g++)
#pragma unroll
            for (int u = 0; u < 2; u++)
#pragma unroll
                for (int p = 0; p < 2; p++) acc[g][u][p] = 0ull;
        for (int k0 = 0; k0 < 512; k0 += 32) {
            float th[8], tw[24];
#pragma unroll
            for (int i = 0; i < 8; i++)
                th[i] = h0s[(size_t)(k0 + row0 + 4 * i) * 256 + bt * 32 + bcol];
#pragma unroll
            for (int i = 0; i < 24; i++) {
                int e = tid + i * 128; int g = e >> 10, r2 = e & 1023, kk = r2 >> 5, c = r2 & 31;
                tw[i] = dWhhT0[(size_t)(k0 + kk) * 1536 + g * 512 + ct * 32 + c];
            }
#pragma unroll
            for (int i = 0; i < 8; i++) Hs[(row0 + 4 * i) * 32 + bcol] = th[i];
#pragma unroll
            for (int i = 0; i < 24; i++) Ws8[tid + i * 128] = pack2(tw[i], tw[i]);
            __syncthreads();
#pragma unroll 8
            for (int kk = 0; kk < 32; kk++) {
                u64 a0 = *(const u64*)&Hs[kk * 32 + 2 * pbg];
                u64 a1 = *(const u64*)&Hs[kk * 32 + 2 * pbg + 16];
#pragma unroll
                for (int g = 0; g < 3; g++)
#pragma unroll
                    for (int u = 0; u < 2; u++) {
                        u64 wp = Ws8[g * 1024 + kk * 32 + cg + 16 * u];
                        fma2(acc[g][u][0], a0, wp);
                        fma2(acc[g][u][1], a1, wp);
                    }
            }
            __syncthreads();
        }
#pragma unroll
        for (int u = 0; u < 2; u++) {
            int j = ct * 32 + cg + 16 * u;
#pragma unroll
            for (int p = 0; p < 2; p++) {
                int b = bt * 32 + 2 * pbg + 16 * p;
                float iax = inp[(size_t)b * istr],       iay = inp[(size_t)b * istr + 1];
                float ibx = inp[(size_t)(b + 1) * istr], iby = inp[(size_t)(b + 1) * istr + 1];
                float2 rH = unpack2(acc[0][u][p]);
                float2 zH = unpack2(acc[1][u][p]);
                float2 nH = unpack2(acc[2][u][p]);
                float2 hold = *(const float2*)&h0s[(size_t)j * 256 + b];
                float2 res;
                {
                    float rX = iax * w0a[0][u] + iay * w0b[0][u] + bi0[0][u];
                    float zX = iax * w0a[1][u] + iay * w0b[1][u] + bi0[1][u];
                    float nX = iax * w0a[2][u] + iay * w0b[2][u] + bi0[2][u];
                    float r = sigf(rH.x + bh0[0][u] + rX);
                    float z = sigf(zH.x + bh0[1][u] + zX);
                    float n = tanhf(nX + r * (nH.x + bh0[2][u]));
                    res.x = (1.f - z) * n + z * hold.x;
                }
                {
                    float rX = ibx * w0a[0][u] + iby * w0b[0][u] + bi0[0][u];
                    float zX = ibx * w0a[1][u] + iby * w0b[1][u] + bi0[1][u];
                    float nX = ibx * w0a[2][u] + iby * w0b[2][u] + bi0[2][u];
                    float r = sigf(rH.y + bh0[0][u] + rX);
                    float z = sigf(zH.y + bh0[1][u] + zX);
                    float n = tanhf(nX + r * (nH.y + bh0[2][u]));
                    res.y = (1.f - z) * n + z * hold.y;
                }
                *(float2*)&h0d[(size_t)j * 256 + b] = res;
            }
        }
        group_barrier(bar, 16);

        // ================= layer 1 (fused x = h0d) =================
        u64 accX[3][2][2];
#pragma unroll
        for (int g = 0; g < 3; g++)
#pragma unroll
            for (int u = 0; u < 2; u++)
#pragma unroll
                for (int p = 0; p < 2; p++) { acc[g][u][p] = 0ull; accX[g][u][p] = 0ull; }
        for (int k0 = 0; k0 < 512; k0 += 32) {
            float th[8], tx[8], tw[24];
#pragma unroll
            for (int i = 0; i < 8; i++) {
                th[i] = h1s[(size_t)(k0 + row0 + 4 * i) * 256 + bt * 32 + bcol];
                tx[i] = h0d[(size_t)(k0 + row0 + 4 * i) * 256 + bt * 32 + bcol];
            }
#pragma unroll
            for (int i = 0; i < 8; i++) {
                Hs[(row0 + 4 * i) * 32 + bcol] = th[i];
                Xs[(row0 + 4 * i) * 32 + bcol] = tx[i];
            }
#pragma unroll
            for (int i = 0; i < 24; i++) {
                int e = tid + i * 128; int g = e >> 10, r2 = e & 1023, kk = r2 >> 5, c = r2 & 31;
                tw[i] = dWhhT1[(size_t)(k0 + kk) * 1536 + g * 512 + ct * 32 + c];
            }
#pragma unroll
            for (int i = 0; i < 24; i++) Ws8[tid + i * 128] = pack2(tw[i], tw[i]);
#pragma unroll
            for (int i = 0; i < 24; i++) {
                int e = tid + i * 128; int g = e >> 10, r2 = e & 1023, kk = r2 >> 5, c = r2 & 31;
                tw[i] = dWihT1[(size_t)(k0 + kk) * 1536 + g * 512 + ct * 32 + c];
            }
#pragma unroll
            for (int i = 0; i < 24; i++) WXs8[tid + i * 128] = pack2(tw[i], tw[i]);
            __syncthreads();
#pragma unroll 4
            for (int kk = 0; kk < 32; kk++) {
                u64 a0 = *(const u64*)&Hs[kk * 32 + 2 * pbg];
                u64 a1 = *(const u64*)&Hs[kk * 32 + 2 * pbg + 16];
                u64 x0 = *(const u64*)&Xs[kk * 32 + 2 * pbg];
                u64 x1 = *(const u64*)&Xs[kk * 32 + 2 * pbg + 16];
#pragma unroll
                for (int g = 0; g < 3; g++)
#pragma unroll
                    for (int u = 0; u < 2; u++) {
                        u64 wp = Ws8[g * 1024 + kk * 32 + cg + 16 * u];
                        fma2(acc[g][u][0], a0, wp);
                        fma2(acc[g][u][1], a1, wp);
                        u64 wxp = WXs8[g * 1024 + kk * 32 + cg + 16 * u];
                        fma2(accX[g][u][0], x0, wxp);
                        fma2(accX[g][u][1], x1, wxp);
                    }
            }
            __syncthreads();
        }
#pragma unroll
        for (int u = 0; u < 2; u++) {
            int j = ct * 32 + cg + 16 * u;
#pragma unroll
            for (int p = 0; p < 2; p++) {
                int b = bt * 32 + 2 * pbg + 16 * p;
                float2 rH = unpack2(acc[0][u][p]);
                float2 zH = unpack2(acc[1][u][p]);
                float2 nH = unpack2(acc[2][u][p]);
                float2 rX = unpack2(accX[0][u][p]);
                float2 zX = unpack2(accX[1][u][p]);
                float2 nX = unpack2(accX[2][u][p]);
                float2 hold = *(const float2*)&h1s[(size_t)j * 256 + b];
                float2 res;
                {
                    float r = sigf(rH.x + bh1[0][u] + rX.x + bi1[0][u]);
                    float z = sigf(zH.x + bh1[1][u] + zX.x + bi1[1][u]);
                    float n = tanhf(nX.x + bi1[2][u] + r * (nH.x + bh1[2][u]));
                    res.x = (1.f - z) * n + z * hold.x;
                }
                {
                    float r = sigf(rH.y + bh1[0][u] + rX.y + bi1[0][u]);
                    float z = sigf(zH.y + bh1[1][u] + zX.y + bi1[1][u]);
                    float n = tanhf(nX.y + bi1[2][u] + r * (nH.y + bh1[2][u]));
                    res.y = (1.f - z) * n + z * hold.y;
                }
                *(float2*)&h1d[(size_t)j * 256 + b] = res;
            }
        }
        group_barrier(bar, 16);

        // ================= fc (one CTA per group) =================
        if (ct == 0) {
            int b = bt * 32 + (tid & 31);
            int q = tid >> 5;
            float s0 = 0.f, s1 = 0.f;
#pragma unroll 8
            for (int jj = q * 128; jj < q * 128 + 128; jj++) {
                float hv = h1d[(size_t)jj * 256 + b];
                s0 += hv * fcW[jj];
                s1 += hv * fcW[512 + jj];
            }
            red[(q * 2 + 0) * 32 + (tid & 31)] = s0;
            red[(q * 2 + 1) * 32 + (tid & 31)] = s1;
            __syncthreads();
            if (tid < 32) {
                float t0 = fcb[0] + red[0 * 32 + tid] + red[2 * 32 + tid] + red[4 * 32 + tid] + red[6 * 32 + tid];
                float t1 = fcb[1] + red[1 * 32 + tid] + red[3 * 32 + tid] + red[5 * 32 + tid] + red[7 * 32 + tid];
                out[(b * 20 + s) * 2 + 0] = t0;
                out[(b * 20 + s) * 2 + 1] = t1;
                dinp[b * 2 + 0] = t0;
                dinp[b * 2 + 1] = t1;
            }
        }
        group_barrier(bar, 16);
    }
}

// ---------------- host ----------------
static float* sym(const void* s) {
    void* p = nullptr;
    cudaGetSymbolAddress(&p, s);
    return (float*)p;
}

extern "C" void kernel_launch(void* const* d_in, const int* in_sizes, int n_in,
                              void* d_out, int out_size) {
    const float* x      = (const float*)d_in[0];
    const float* stok   = (const float*)d_in[1];
    const float* eWih0  = (const float*)d_in[2];
    const float* eWhh0  = (const float*)d_in[3];
    const float* eBih0  = (const float*)d_in[4];
    const float* eBhh0  = (const float*)d_in[5];
    const float* eWih1  = (const float*)d_in[6];
    const float* eWhh1  = (const float*)d_in[7];
    const float* eBih1  = (const float*)d_in[8];
    const float* eBhh1  = (const float*)d_in[9];
    const float* dWih0  = (const float*)d_in[10];
    const float* dWhh0  = (const float*)d_in[11];
    const float* dBih0  = (const float*)d_in[12];
    const float* dBhh0  = (const float*)d_in[13];
    const float* dWih1  = (const float*)d_in[14];
    const float* dWhh1  = (const float*)d_in[15];
    const float* dBih1  = (const float*)d_in[16];
    const float* dBhh1  = (const float*)d_in[17];
    const float* fcW    = (const float*)d_in[18];
    const float* fcb    = (const float*)d_in[19];
    float* out = (float*)d_out;

    float* gi    = sym(g_gi);
    float* y0    = sym(g_y0);
    float* h0    = sym(g_h0);
    float* h1    = sym(g_h1);
    float* hd0   = sym(g_hd0);
    float* hd1   = sym(g_hd1);
    float* dinp  = sym(g_dinp);
    float* WihT0 = sym(g_WihT0);
    float* WihT1 = sym(g_WihT1);
    float* WhhT0 = sym(g_WhhT0);
    float* WhhT1 = sym(g_WhhT1);
    float* dWhhT0 = sym(g_dWhhT0);
    float* dWihT1 = sym(g_dWihT1);
    float* dWhhT1 = sym(g_dWhhT1);
    u64*   ebar  = (u64*)sym(g_ebar);
    u64*   dbar  = (u64*)sym(g_dbar);

    const int ENC_SMEM = 131072 + 65536 + 32768;            // 229,376 B
    const int DEC_SMEM = 24576 * 2 + 4096 * 2 + 1024;       // 58,368 B
    cudaFuncSetAttribute(k_enc_layer, cudaFuncAttributeMaxDynamicSharedMemorySize, ENC_SMEM);
    cudaFuncSetAttribute(k_decoder,   cudaFuncAttributeMaxDynamicSharedMemorySize, DEC_SMEM);

    dim3 tb(32, 8);
    // launch order: ncu empirically captures launch #4 -> k_gi_gemm<1>
    k_prep_all<<<dim3(16, 48, 12), tb>>>(eWih0, WihT0, eWhh0, WhhT0,
                                         eWih1, WihT1, eWhh1, WhhT1,
                                         dWhh0, dWhhT0, dWih1, dWihT1,
                                         dWhh1, dWhhT1, h0, h1);                    // 1
    k_gi_gemm<0><<<dim3(6, 4, 1024), 256>>>(x, WihT0, eBih0, gi, 64);               // 2
    k_enc_layer<<<128, 256, ENC_SMEM>>>(WhhT0, eBhh0, gi, h0, y0, ebar);            // 3
    k_gi_gemm<1><<<dim3(6, 4, 1024), 256>>>(y0, WihT1, eBih1, gi, 512);             // 4 <- ncu
    k_enc_layer<<<128, 256, ENC_SMEM>>>(WhhT1, eBhh1, gi, h1, nullptr, ebar);       // 5
    cudaMemcpyAsync(hd0, h0, 131072 * sizeof(float), cudaMemcpyDeviceToDevice);
    cudaMemcpyAsync(hd1, h1, 131072 * sizeof(float), cudaMemcpyDeviceToDevice);
    k_decoder<<<128, 128, DEC_SMEM>>>(dWhhT0, dBhh0, dWih0, dBih0, dWihT1, dWhhT1,
                                      dBih1, dBhh1, fcW, fcb, stok, hd0, hd1, dinp, out, dbar);
}

// round 14
// speedup vs baseline: 1.0742x; 1.0742x over previous
#include <cuda_runtime.h>
#include <math.h>

typedef unsigned long long u64;

// ---------------- device scratch (allocation-free) ----------------
__device__ float g_gi[2ull*512*768*256];     // [D][T][768][B]  (reused per layer)
__device__ float g_y0[512ull*512*256];       // [T][512][B] layer0 output (transposed)
__device__ float g_h0[2][2*256*256];         // [phase][D][J=256][B]
__device__ float g_h1[2][2*256*256];
__device__ float g_hd0[2][512*256];          // [phase][J=512][B]
__device__ float g_hd1[2][512*256];
__device__ float g_dinp[256*2];              // decoder feedback [B][2]
__device__ float g_WihT0[2*64*768];
__device__ float g_WihT1[2*512*768];
__device__ float g_WhhT0[2*256*768];
__device__ float g_WhhT1[2*256*768];
__device__ float g_dWhhT0[512*1536];
__device__ float g_dWihT1[512*1536];
__device__ float g_dWhhT1[512*1536];
__device__ u64   g_ebar[16*16];              // encoder: 16 groups, 128B apart
__device__ u64   g_dbar[8*16];               // decoder: 8 groups

// ---------------- f32x2 helpers ----------------
__device__ __forceinline__ u64 pack2(float lo, float hi) {
    u64 r; asm("mov.b64 %0, {%1,%2};" : "=l"(r) : "f"(lo), "f"(hi)); return r;
}
__device__ __forceinline__ void fma2(u64& d, u64 a, u64 b) {
    asm("fma.rn.f32x2 %0, %1, %2, %3;" : "=l"(d) : "l"(a), "l"(b), "l"(d));
}
__device__ __forceinline__ float2 unpack2(u64 v) {
    float2 f; asm("mov.b64 {%0,%1}, %2;" : "=f"(f.x), "=f"(f.y) : "l"(v)); return f;
}
__device__ __forceinline__ float sigf(float x) { return 1.f / (1.f + __expf(-x)); }

// ---------------- group barrier (monotonic ticket, per-group counter) ------
__device__ __forceinline__ void group_barrier(u64* bar, unsigned n) {
    __syncthreads();
    if (threadIdx.x == 0) {
        __threadfence();
        u64 t = atomicAdd(bar, 1ULL);
        u64 target = (t / n + 1ULL) * (u64)n;
        u64 v;
        do {
            asm volatile("ld.acquire.gpu.global.u64 %0, [%1];" : "=l"(v) : "l"(bar));
        } while (v < target);
    }
    __syncthreads();
}

// ---------------- transpose helper (32x32 tile) ----------------
__device__ __forceinline__ void tile_transpose(const float* __restrict__ in,
                                               float* __restrict__ out,
                                               int N, int K, int bx, int by) {
    __shared__ float t[32][33];
    int k0 = bx * 32, n0 = by * 32;
    int x = threadIdx.x, y = threadIdx.y;
#pragma unroll
    for (int j = 0; j < 32; j += 8) {
        int n = n0 + y + j;
        if (n < N && k0 + x < K) t[y + j][x] = in[(size_t)n * K + k0 + x];
    }
    __syncthreads();
#pragma unroll
    for (int j = 0; j < 32; j += 8) {
        int k = k0 + y + j;
        if (k < K && n0 + x < N) out[(size_t)k * N + n0 + x] = t[x][y + j];
    }
}

// ---------------- single prep kernel: all transposes + h zero --------------
// grid (16, 48, 12), block (32, 8)
__global__ void k_prep_all(const float* __restrict__ eWih0, float* __restrict__ WihT0,
                           const float* __restrict__ eWhh0, float* __restrict__ WhhT0,
                           const float* __restrict__ eWih1, float* __restrict__ WihT1,
                           const float* __restrict__ eWhh1, float* __restrict__ WhhT1,
                           const float* __restrict__ dWhh0, float* __restrict__ dWhhT0,
                           const float* __restrict__ dWih1, float* __restrict__ dWihT1,
                           const float* __restrict__ dWhh1, float* __restrict__ dWhhT1,
                           float* __restrict__ h0, float* __restrict__ h1) {
    int z = blockIdx.z, bx = blockIdx.x, by = blockIdx.y;
    if (z < 2) {
        if (bx < 2 && by < 24)
            tile_transpose(eWih0 + (size_t)z * 768 * 64, WihT0 + (size_t)z * 64 * 768,
                           768, 64, bx, by);
    } else if (z < 4) {
        if (bx < 8 && by < 24)
            tile_transpose(eWhh0 + (size_t)(z - 2) * 768 * 256, WhhT0 + (size_t)(z - 2) * 256 * 768,
                           768, 256, bx, by);
    } else if (z < 6) {
        if (by < 24)
            tile_transpose(eWih1 + (size_t)(z - 4) * 768 * 512, WihT1 + (size_t)(z - 4) * 512 * 768,
                           768, 512, bx, by);
    } else if (z < 8) {
        if (bx < 8 && by < 24)
            tile_transpose(eWhh1 + (size_t)(z - 6) * 768 * 256, WhhT1 + (size_t)(z - 6) * 256 * 768,
                           768, 256, bx, by);
    } else if (z < 11) {
        const float* in = (z == 8) ? dWhh0 : (z == 9) ? dWih1 : dWhh1;
        float* out      = (z == 8) ? dWhhT0 : (z == 9) ? dWihT1 : dWhhT1;
        tile_transpose(in, out, 1536, 512, bx, by);
    } else {
        int flat = ((bx * 48 + by) * 256) + threadIdx.y * 32 + threadIdx.x;
        for (int i = flat; i < 131072; i += 16 * 48 * 256) { h0[i] = 0.f; h1[i] = 0.f; }
    }
}

// ---------------- gi GEMM: 8b x 8c thread tile, 1.0 B/MAC smem -------------
// out[d][t][col][b] = sum_k A[t,b,k] * W[d][col][k] + bih[d][col]
// MODE 0: A = x [B][T][64] (K=64); MODE 1: A = y0 [T][512][B] (K=512)
// block 128 thr: cg = tid&15 (8 c at 8*cg), bg = tid>>4 (8 b at 8*bg).
// inner k: 2 LDS.128 (a) + 2 LDS.128 (w pairs) + 8 pack + 32 FFMA2.
// epilogue restaged through smem for coalesced 128B stores.
template<int MODE>
__global__ __launch_bounds__(128, 4)
void k_gi_gemm(const float* __restrict__ A, const float* __restrict__ WT,
               const float* __restrict__ bih, float* __restrict__ out, int K) {
    __shared__ float smA[32 * 68 + 32 * 132];   // As | Ws ; reused as smOut
    float* As = smA;                  // [32][68]
    float* Ws = smA + 32 * 68;        // [32][132]
    float* smOut = smA;               // [64][67] per chunk (4288 <= 6400 floats)
    int ct = blockIdx.x, bt = blockIdx.y;
    int d = blockIdx.z >> 9, t = blockIdx.z & 511;
    int tid = threadIdx.x;
    int cg = tid & 15;                // 8 c at 8*cg
    int bg = tid >> 4;                // 8 b at 8*bg
    const float* Wd = WT + (size_t)d * K * 768;
    u64 acc[8][4];
#pragma unroll
    for (int i = 0; i < 8; i++)
#pragma unroll
        for (int j = 0; j < 4; j++) acc[i][j] = 0ull;

    for (int k0 = 0; k0 < K; k0 += 32) {
        if (MODE == 0) {
#pragma unroll
            for (int i = 0; i < 16; i++) {
                int e = tid + i * 128; int b = e >> 5, k = e & 31;
                As[k * 68 + b] = A[((size_t)(bt * 64 + b) * 512 + t) * 64 + k0 + k];
            }
        } else {
#pragma unroll
            for (int i = 0; i < 16; i++) {
                int e = tid + i * 128; int kk = e >> 6, b = e & 63;
                As[kk * 68 + b] = A[((size_t)t * 512 + k0 + kk) * 256 + bt * 64 + b];
            }
        }
#pragma unroll
        for (int i = 0; i < 32; i++) {
            int e = tid + i * 128; int kk = e >> 7, c = e & 127;
            Ws[kk * 132 + c] = Wd[(size_t)(k0 + kk) * 768 + ct * 128 + c];
        }
        __syncthreads();
#pragma unroll 8
        for (int kk = 0; kk < 32; kk++) {
            ulonglong2 wv0 = *(const ulonglong2*)&Ws[kk * 132 + 8 * cg];
            ulonglong2 wv1 = *(const ulonglong2*)&Ws[kk * 132 + 8 * cg + 4];
            float4 av0 = *(const float4*)&As[kk * 68 + 8 * bg];
            float4 av1 = *(const float4*)&As[kk * 68 + 8 * bg + 4];
            u64 ad[8];
            ad[0] = pack2(av0.x, av0.x); ad[1] = pack2(av0.y, av0.y);
            ad[2] = pack2(av0.z, av0.z); ad[3] = pack2(av0.w, av0.w);
            ad[4] = pack2(av1.x, av1.x); ad[5] = pack2(av1.y, av1.y);
            ad[6] = pack2(av1.z, av1.z); ad[7] = pack2(av1.w, av1.w);
            u64 w[4] = {wv0.x, wv0.y, wv1.x, wv1.y};
#pragma unroll
            for (int i = 0; i < 8; i++)
#pragma unroll
                for (int j = 0; j < 4; j++) fma2(acc[i][j], ad[i], w[j]);
        }
        __syncthreads();
    }

    // ---- epilogue: two chunks of 64 c-rows, restaged for coalesced stores --
    float* outp = out + (size_t)(d * 512 + t) * 768 * 256;
    float bb[8];
#pragma unroll
    for (int q = 0; q < 8; q++) bb[q] = bih[d * 768 + ct * 128 + 8 * cg + q];
#pragma unroll
    for (int chunk = 0; chunk < 2; chunk++) {
        __syncthreads();   // smOut aliases As/Ws (dead after k-loop / prev chunk read)
#pragma unroll
        for (int j2 = 0; j2 < 2; j2++) {
            int j = 2 * chunk + j2;
#pragma unroll
            for (int i = 0; i < 8; i++) {
                float2 v = unpack2(acc[i][j]);
                int r0 = 4 * cg + 2 * j2;
                smOut[(size_t)r0 * 67 + 8 * bg + i]       = v.x + bb[2 * j];
                smOut[(size_t)(r0 + 1) * 67 + 8 * bg + i] = v.y + bb[2 * j + 1];
            }
        }
        __syncthreads();
        // rows r: cg=r>>2, off=r&3 -> c = ct*128 + 8*(r>>2) + 4*chunk_off... 
        // c = ct*128 + 8*(r>>2) + 2*(2*chunk + ((r>>1)&1)) + (r&1)
#pragma unroll
        for (int i = 0; i < 32; i++) {
            int e = tid + i * 128;
            int r = e >> 6, b = e & 63;
            int c = ct * 128 + 8 * (r >> 2) + 4 * chunk + (r & 3);
            outp[(size_t)c * 256 + bt * 64 + b] = smOut[(size_t)r * 67 + b];
        }
    }
}

// ---------------- persistent encoder layer (R12 version, unchanged) --------
// 128 CTAs x 256 threads. CTA = (jt 0..7, group 0..15), group=(bt 0..7, d 0..1).
__global__ __launch_bounds__(256, 1)
void k_enc_layer(const float* __restrict__ WhhT, const float* __restrict__ bhh,
                 const float* __restrict__ gi, float* __restrict__ hbuf,
                 float* __restrict__ yout, u64* __restrict__ barBase) {
    extern __shared__ char sm[];
    u64*   WdA = (u64*)sm;                       // [256][32][2] g0,g1 dup
    u64*   WdB = (u64*)(sm + 131072);            // [256][32]   g2 dup
    float* Hs  = (float*)(sm + 196608);          // [256][32]
    int bx = blockIdx.x;
    int jt = bx & 7, grp = bx >> 3;
    int bt = grp & 7, d = grp >> 3;
    u64* bar = barBase + grp * 16;
    int tid = threadIdx.x;
    int pbg = tid & 7;
    int cw  = tid >> 3;
    int j = jt * 32 + cw;
    int bbase = bt * 32 + 4 * pbg;

    const float* Wp = WhhT + (size_t)d * 256 * 768;
#pragma unroll 4
    for (int i = 0; i < 96; i++) {
        int e = tid + i * 256;
        int c = e & 31, k = (e >> 5) & 255, g = e >> 13;
        float w = Wp[(size_t)k * 768 + g * 256 + jt * 32 + c];
        u64 wd = pack2(w, w);
        if (g < 2) WdA[(k * 32 + c) * 2 + g] = wd;
        else       WdB[k * 32 + c] = wd;
    }
    const float* bh = bhh + d * 768;
    float bhv[3];
#pragma unroll
    for (int g = 0; g < 3; g++) bhv[g] = bh[g * 256 + j];

    int row0 = tid >> 5, bcol = tid & 31;

    for (int s = 0; s < 512; s++) {
        const float* hsrc = hbuf + (size_t)(s & 1) * 131072 + (size_t)d * 65536;
        float*       hdst = hbuf + (size_t)((s + 1) & 1) * 131072 + (size_t)d * 65536;
        int t = d ? (511 - s) : s;
        const float* gp = gi + (size_t)(d * 512 + t) * 768 * 256;
        float4 gx[3];
#pragma unroll
        for (int g = 0; g < 3; g++)
            gx[g] = *(const float4*)&gp[((size_t)(g * 256 + j)) * 256 + bbase];
        float tmp[32];
#pragma unroll
        for (int i = 0; i < 32; i++)
            tmp[i] = hsrc[(size_t)(row0 + 8 * i) * 256 + bt * 32 + bcol];
#pragma unroll
        for (int i = 0; i < 32; i++)
            Hs[(row0 + 8 * i) * 32 + bcol] = tmp[i];
        __syncthreads();

        u64 acc[3][2];
#pragma unroll
        for (int g = 0; g < 3; g++) { acc[g][0] = 0ull; acc[g][1] = 0ull; }

#pragma unroll 16
        for (int kk = 0; kk < 256; kk++) {
            ulonglong2 av  = *(const ulonglong2*)&Hs[kk * 32 + 4 * pbg];
            ulonglong2 w01 = *(const ulonglong2*)&WdA[((size_t)kk * 32 + cw) * 2];
            u64        w2  = WdB[kk * 32 + cw];
            fma2(acc[0][0], av.x, w01.x); fma2(acc[0][1], av.y, w01.x);
            fma2(acc[1][0], av.x, w01.y); fma2(acc[1][1], av.y, w01.y);
            fma2(acc[2][0], av.x, w2);    fma2(acc[2][1], av.y, w2);
        }
        float4 hold = *(const float4*)&Hs[j * 32 + 4 * pbg];
        float hlds[4] = {hold.x, hold.y, hold.z, hold.w};
        float rh[4], zh[4], nh[4];
        { float2 a = unpack2(acc[0][0]), b2 = unpack2(acc[0][1]);
          rh[0] = a.x; rh[1] = a.y; rh[2] = b2.x; rh[3] = b2.y; }
        { float2 a = unpack2(acc[1][0]), b2 = unpack2(acc[1][1]);
          zh[0] = a.x; zh[1] = a.y; zh[2] = b2.x; zh[3] = b2.y; }
        { float2 a = unpack2(acc[2][0]), b2 = unpack2(acc[2][1]);
          nh[0] = a.x; nh[1] = a.y; nh[2] = b2.x; nh[3] = b2.y; }
        float gxr[4] = {gx[0].x, gx[0].y, gx[0].z, gx[0].w};
        float gxz[4] = {gx[1].x, gx[1].y, gx[1].z, gx[1].w};
        float gxn[4] = {gx[2].x, gx[2].y, gx[2].z, gx[2].w};
        float res[4];
#pragma unroll
        for (int q = 0; q < 4; q++) {
            float r = sigf(rh[q] + bhv[0] + gxr[q]);
            float z = sigf(zh[q] + bhv[1] + gxz[q]);
            float n = tanhf(gxn[q] + r * (nh[q] + bhv[2]));
            res[q] = (1.f - z) * n + z * hlds[q];
        }
        float4 out4 = make_float4(res[0], res[1], res[2], res[3]);
        *(float4*)&hdst[(size_t)j * 256 + bbase] = out4;
        if (yout)
            *(float4*)&yout[((size_t)t * 512 + d * 256 + j) * 256 + bbase] = out4;
        group_barrier(bar, 8);
    }
}

// ---------------- persistent decoder (20 steps, 2 layers + fc) -------------
__global__ __launch_bounds__(128, 1)
void k_decoder(const float* __restrict__ dWhhT0, const float* __restrict__ dBhh0,
               const float* __restrict__ dWih0,  const float* __restrict__ dBih0,
               const float* __restrict__ dWihT1, const float* __restrict__ dWhhT1,
               const float* __restrict__ dBih1,  const float* __restrict__ dBhh1,
               const float* __restrict__ fcW,    const float* __restrict__ fcb,
               const float* __restrict__ stok,
               float* __restrict__ hd0, float* __restrict__ hd1,
               float* __restrict__ dinp, float* __restrict__ out,
               u64* __restrict__ barBase) {
    extern __shared__ char dsm[];
    u64*   Ws8  = (u64*)dsm;                       // 24576 B
    u64*   WXs8 = (u64*)(dsm + 24576);             // 24576 B
    float* Hs   = (float*)(dsm + 49152);           // 4096 B
    float* Xs   = (float*)(dsm + 53248);           // 4096 B
    float* red  = (float*)(dsm + 57344);           // 1024 B
    int bx = blockIdx.x;
    int ct = bx & 15, bt = bx >> 4;
    u64* bar = barBase + bt * 16;
    int tid = threadIdx.x;
    int pbg = tid & 7, cg = tid >> 3;
    int row0 = tid >> 5, bcol = tid & 31;

    float w0a[3][2], w0b[3][2], bi0[3][2], bh0[3][2], bi1[3][2], bh1[3][2];
#pragma unroll
    for (int g = 0; g < 3; g++)
#pragma unroll
        for (int u = 0; u < 2; u++) {
            int c = g * 512 + ct * 32 + cg + 16 * u;
            w0a[g][u] = dWih0[c * 2];
            w0b[g][u] = dWih0[c * 2 + 1];
            bi0[g][u] = dBih0[c];
            bh0[g][u] = dBhh0[c];
            bi1[g][u] = dBih1[c];
            bh1[g][u] = dBhh1[c];
        }

    for (int s = 0; s < 20; s++) {
        const float* h0s = hd0 + (size_t)(s & 1) * 131072;
        float*       h0d = hd0 + (size_t)((s + 1) & 1) * 131072;
        const float* h1s = hd1 + (size_t)(s & 1) * 131072;
        float*       h1d = hd1 + (size_t)((s + 1) & 1) * 131072;
        const float* inp = s ? dinp : stok;
        int istr = s ? 2 : 0;

        // ================= layer 0 =================
        u64 acc[3][2][2];
#pragma unroll
        for (int g = 0; g < 3; g++)
#pragma unroll
            for (int u = 0; u < 2; u++)
#pragma unroll
                for (int p = 0; p < 2; p++) acc[g][u][p] = 0ull;
        for (int k0 = 0; k0 < 512; k0 += 32) {
            float th[8], tw[24];
#pragma unroll
            for (int i = 0; i < 8; i++)
                th[i] = h0s[(size_t)(k0 + row0 + 4 * i) * 256 + bt * 32 + bcol];
#pragma unroll
            for (int i = 0; i < 24; i++) {
                int e = tid + i * 128; int g = e >> 10, r2 = e & 1023, kk = r2 >> 5, c = r2 & 31;
                tw[i] = dWhhT0[(size_t)(k0 + kk) * 1536 + g * 512 + ct * 32 + c];
            }
#pragma unroll
            for (int i = 0; i < 8; i++) Hs[(row0 + 4 * i) * 32 + bcol] = th[i];
#pragma unroll
            for (int i = 0; i < 24; i++) Ws8[tid + i * 128] = pack2(tw[i], tw[i]);
            __syncthreads();
#pragma unroll 8
            for (int kk = 0; kk < 32; kk++) {
                u64 a0 = *(const u64*)&Hs[kk * 32 + 2 * pbg];
                u64 a1 = *(const u64*)&Hs[kk * 32 + 2 * pbg + 16];
#pragma unroll
                for (int g = 0; g < 3; g++)
#pragma unroll
                    for (int u = 0; u < 2; u++) {
                        u64 wp = Ws8[g * 1024 + kk * 32 + cg + 16 * u];
                        fma2(acc[g][u][0], a0, wp);
                        fma2(acc[g][u][1], a1, wp);
                    }
            }
            __syncthreads();
        }
#pragma unroll
        for (int u = 0; u < 2; u++) {
            int j = ct * 32 + cg + 16 * u;
#pragma unroll
            for (int p = 0; p < 2; p++) {
                int b = bt * 32 + 2 * pbg + 16 * p;
                float iax = inp[(size_t)b * istr],       iay = inp[(size_t)b * istr + 1];
                float ibx = inp[(size_t)(b + 1) * istr], iby = inp[(size_t)(b + 1) * istr + 1];
                float2 rH = unpack2(acc[0][u][p]);
                float2 zH = unpack2(acc[1][u][p]);
                float2 nH = unpack2(acc[2][u][p]);
                float2 hold = *(const float2*)&h0s[(size_t)j * 256 + b];
                float2 res;
                {
                    float rX = iax * w0a[0][u] + iay * w0b[0][u] + bi0[0][u];
                    float zX = iax * w0a[1][u] + iay * w0b[1][u] + bi0[1][u];
                    float nX = iax * w0a[2][u] + iay * w0b[2][u] + bi0[2][u];
                    float r = sigf(rH.x + bh0[0][u] + rX);
                    float z = sigf(zH.x + bh0[1][u] + zX);
                    float n = tanhf(nX + r * (nH.x + bh0[2][u]));
                    res.x = (1.f - z) * n + z * hold.x;
                }
                {
                    float rX = ibx * w0a[0][u] + iby * w0b[0][u] + bi0[0][u];
                    float zX = ibx * w0a[1][u] + iby * w0b[1][u] + bi0[1][u];
                    float nX = ibx * w0a[2][u] + iby * w0b[2][u] + bi0[2][u];
                    float r = sigf(rH.y + bh0[0][u] + rX);
                    float z = sigf(zH.y + bh0[1][u] + zX);
                    float n = tanhf(nX + r * (nH.y + bh0[2][u]));
                    res.y = (1.f - z) * n + z * hold.y;
                }
                *(float2*)&h0d[(size_t)j * 256 + b] = res;
            }
        }
        group_barrier(bar, 16);

        // ================= layer 1 (fused x = h0d) =================
        u64 accX[3][2][2];
#pragma unroll
        for (int g = 0; g < 3; g++)
#pragma unroll
            for (int u = 0; u < 2; u++)
#pragma unroll
                for (int p = 0; p < 2; p++) { acc[g][u][p] = 0ull; accX[g][u][p] = 0ull; }
        for (int k0 = 0; k0 < 512; k0 += 32) {
            float th[8], tx[8], tw[24];
#pragma unroll
            for (int i = 0; i < 8; i++) {
                th[i] = h1s[(size_t)(k0 + row0 + 4 * i) * 256 + bt * 32 + bcol];
                tx[i] = h0d[(size_t)(k0 + row0 + 4 * i) * 256 + bt * 32 + bcol];
            }
#pragma unroll
            for (int i = 0; i < 8; i++) {
                Hs[(row0 + 4 * i) * 32 + bcol] = th[i];
                Xs[(row0 + 4 * i) * 32 + bcol] = tx[i];
            }
#pragma unroll
            for (int i = 0; i < 24; i++) {
                int e = tid + i * 128; int g = e >> 10, r2 = e & 1023, kk = r2 >> 5, c = r2 & 31;
                tw[i] = dWhhT1[(size_t)(k0 + kk) * 1536 + g * 512 + ct * 32 + c];
            }
#pragma unroll
            for (int i = 0; i < 24; i++) Ws8[tid + i * 128] = pack2(tw[i], tw[i]);
#pragma unroll
            for (int i = 0; i < 24; i++) {
                int e = tid + i * 128; int g = e >> 10, r2 = e & 1023, kk = r2 >> 5, c = r2 & 31;
                tw[i] = dWihT1[(size_t)(k0 + kk) * 1536 + g * 512 + ct * 32 + c];
            }
#pragma unroll
            for (int i = 0; i < 24; i++) WXs8[tid + i * 128] = pack2(tw[i], tw[i]);
            __syncthreads();
#pragma unroll 4
            for (int kk = 0; kk < 32; kk++) {
                u64 a0 = *(const u64*)&Hs[kk * 32 + 2 * pbg];
                u64 a1 = *(const u64*)&Hs[kk * 32 + 2 * pbg + 16];
                u64 x0 = *(const u64*)&Xs[kk * 32 + 2 * pbg];
                u64 x1 = *(const u64*)&Xs[kk * 32 + 2 * pbg + 16];
#pragma unroll
                for (int g = 0; g < 3; g++)
#pragma unroll
                    for (int u = 0; u < 2; u++) {
                        u64 wp = Ws8[g * 1024 + kk * 32 + cg + 16 * u];
                        fma2(acc[g][u][0], a0, wp);
                        fma2(acc[g][u][1], a1, wp);
                        u64 wxp = WXs8[g * 1024 + kk * 32 + cg + 16 * u];
                        fma2(accX[g][u][0], x0, wxp);
                        fma2(accX[g][u][1], x1, wxp);
                    }
            }
            __syncthreads();
        }
#pragma unroll
        for (int u = 0; u < 2; u++) {
            int j = ct * 32 + cg + 16 * u;
#pragma unroll
            for (int p = 0; p < 2; p++) {
                int b = bt * 32 + 2 * pbg + 16 * p;
                float2 rH = unpack2(acc[0][u][p]);
                float2 zH = unpack2(acc[1][u][p]);
                float2 nH = unpack2(acc[2][u][p]);
                float2 rX = unpack2(accX[0][u][p]);
                float2 zX = unpack2(accX[1][u][p]);
                float2 nX = unpack2(accX[2][u][p]);
                float2 hold = *(const float2*)&h1s[(size_t)j * 256 + b];
                float2 res;
                {
                    float r = sigf(rH.x + bh1[0][u] + rX.x + bi1[0][u]);
                    float z = sigf(zH.x + bh1[1][u] + zX.x + bi1[1][u]);
                    float n = tanhf(nX.x + bi1[2][u] + r * (nH.x + bh1[2][u]));
                    res.x = (1.f - z) * n + z * hold.x;
                }
                {
                    float r = sigf(rH.y + bh1[0][u] + rX.y + bi1[0][u]);
                    float z = sigf(zH.y + bh1[1][u] + zX.y + bi1[1][u]);
                    float n = tanhf(nX.y + bi1[2][u] + r * (nH.y + bh1[2][u]));
                    res.y = (1.f - z) * n + z * hold.y;
                }
                *(float2*)&h1d[(size_t)j * 256 + b] = res;
            }
        }
        group_barrier(bar, 16);

        // ================= fc (one CTA per group) =================
        if (ct == 0) {
            int b = bt * 32 + (tid & 31);
            int q = tid >> 5;
            float s0 = 0.f, s1 = 0.f;
#pragma unroll 8
            for (int jj = q * 128; jj < q * 128 + 128; jj++) {
                float hv = h1d[(size_t)jj * 256 + b];
                s0 += hv * fcW[jj];
                s1 += hv * fcW[512 + jj];
            }
            red[(q * 2 + 0) * 32 + (tid & 31)] = s0;
            red[(q * 2 + 1) * 32 + (tid & 31)] = s1;
            __syncthreads();
            if (tid < 32) {
                float t0 = fcb[0] + red[0 * 32 + tid] + red[2 * 32 + tid] + red[4 * 32 + tid] + red[6 * 32 + tid];
                float t1 = fcb[1] + red[1 * 32 + tid] + red[3 * 32 + tid] + red[5 * 32 + tid] + red[7 * 32 + tid];
                out[(b * 20 + s) * 2 + 0] = t0;
                out[(b * 20 + s) * 2 + 1] = t1;
                dinp[b * 2 + 0] = t0;
                dinp[b * 2 + 1] = t1;
            }
        }
        group_barrier(bar, 16);
    }
}

// ---------------- host ----------------
static float* sym(const void* s) {
    void* p = nullptr;
    cudaGetSymbolAddress(&p, s);
    return (float*)p;
}

extern "C" void kernel_launch(void* const* d_in, const int* in_sizes, int n_in,
                              void* d_out, int out_size) {
    const float* x      = (const float*)d_in[0];
    const float* stok   = (const float*)d_in[1];
    const float* eWih0  = (const float*)d_in[2];
    const float* eWhh0  = (const float*)d_in[3];
    const float* eBih0  = (const float*)d_in[4];
    const float* eBhh0  = (const float*)d_in[5];
    const float* eWih1  = (const float*)d_in[6];
    const float* eWhh1  = (const float*)d_in[7];
    const float* eBih1  = (const float*)d_in[8];
    const float* eBhh1  = (const float*)d_in[9];
    const float* dWih0  = (const float*)d_in[10];
    const float* dWhh0  = (const float*)d_in[11];
    const float* dBih0  = (const float*)d_in[12];
    const float* dBhh0  = (const float*)d_in[13];
    const float* dWih1  = (const float*)d_in[14];
    const float* dWhh1  = (const float*)d_in[15];
    const float* dBih1  = (const float*)d_in[16];
    const float* dBhh1  = (const float*)d_in[17];
    const float* fcW    = (const float*)d_in[18];
    const float* fcb    = (const float*)d_in[19];
    float* out = (float*)d_out;

    float* gi    = sym(g_gi);
    float* y0    = sym(g_y0);
    float* h0    = sym(g_h0);
    float* h1    = sym(g_h1);
    float* hd0   = sym(g_hd0);
    float* hd1   = sym(g_hd1);
    float* dinp  = sym(g_dinp);
    float* WihT0 = sym(g_WihT0);
    float* WihT1 = sym(g_WihT1);
    float* WhhT0 = sym(g_WhhT0);
    float* WhhT1 = sym(g_WhhT1);
    float* dWhhT0 = sym(g_dWhhT0);
    float* dWihT1 = sym(g_dWihT1);
    float* dWhhT1 = sym(g_dWhhT1);
    u64*   ebar  = (u64*)sym(g_ebar);
    u64*   dbar  = (u64*)sym(g_dbar);

    const int ENC_SMEM = 131072 + 65536 + 32768;            // 229,376 B
    const int DEC_SMEM = 24576 * 2 + 4096 * 2 + 1024;       // 58,368 B
    cudaFuncSetAttribute(k_enc_layer, cudaFuncAttributeMaxDynamicSharedMemorySize, ENC_SMEM);
    cudaFuncSetAttribute(k_decoder,   cudaFuncAttributeMaxDynamicSharedMemorySize, DEC_SMEM);

    dim3 tb(32, 8);
    // launch order: ncu empirically captures launch #4 -> k_gi_gemm<1>
    k_prep_all<<<dim3(16, 48, 12), tb>>>(eWih0, WihT0, eWhh0, WhhT0,
                                         eWih1, WihT1, eWhh1, WhhT1,
                                         dWhh0, dWhhT0, dWih1, dWihT1,
                                         dWhh1, dWhhT1, h0, h1);                    // 1
    k_gi_gemm<0><<<dim3(6, 4, 1024), 128>>>(x, WihT0, eBih0, gi, 64);               // 2
    k_enc_layer<<<128, 256, ENC_SMEM>>>(WhhT0, eBhh0, gi, h0, y0, ebar);            // 3
    k_gi_gemm<1><<<dim3(6, 4, 1024), 128>>>(y0, WihT1, eBih1, gi, 512);             // 4 <- ncu
    k_enc_layer<<<128, 256, ENC_SMEM>>>(WhhT1, eBhh1, gi, h1, nullptr, ebar);       // 5
    cudaMemcpyAsync(hd0, h0, 131072 * sizeof(float), cudaMemcpyDeviceToDevice);
    cudaMemcpyAsync(hd1, h1, 131072 * sizeof(float), cudaMemcpyDeviceToDevice);
    k_decoder<<<128, 128, DEC_SMEM>>>(dWhhT0, dBhh0, dWih0, dBih0, dWihT1, dWhhT1,
                                      dBih1, dBhh1, fcW, fcb, stok, hd0, hd1, dinp, out, dbar);
}